// round 6
// baseline (speedup 1.0000x reference)
#include <cuda_runtime.h>
#include <math.h>

#define NU 100000
#define NI 50000
#define NE 120000
#define NR 32
#define DM 64
#define NEDGE 1000000
#define NCF 1000000

#define SEG_U 120000
#define SEG_I 220000
#define NSEG 270000
#define SCAN_N 270001
#define SCAN_BLK 1024
#define SCAN_NBLK 264

__device__ int   g_cnt[SCAN_NBLK * SCAN_BLK];
__device__ int   g_off[SCAN_NBLK * SCAN_BLK + 1];
__device__ int   g_cur[NSEG];
__device__ int   g_perm[NEDGE + 2 * NCF];   // holds PAYLOADS, not edge ids
__device__ int   g_bsum[SCAN_BLK];
__device__ int   g_boff[SCAN_BLK];

__device__ float g_entA[NE * DM];
__device__ float g_entB[NE * DM];
__device__ float g_rel[NI * DM];
__device__ float g_relkg[NI * DM];
__device__ float g_u[NU * DM];
__device__ float g_ucf0[NU * DM];
__device__ float g_ucf1[NU * DM];
__device__ float g_icf0[NI * DM];
__device__ float g_icf1[NI * DM];
__device__ float g_p[NCF];
__device__ float g_pcf[NCF];

__device__ __forceinline__ float warpsum(float v) {
    #pragma unroll
    for (int o = 16; o; o >>= 1) v += __shfl_xor_sync(0xffffffffu, v, o);
    return v;
}
__device__ __forceinline__ float lrelu(float x) { return x > 0.f ? x : 0.01f * x; }
__device__ __forceinline__ float sigmoidf(float x) { return 1.f / (1.f + __expf(-x)); }

__global__ void k_init(const float* __restrict__ ue, const float* __restrict__ ee,
                       const float* __restrict__ cf, float* __restrict__ out) {
    const int total = (NE + NU + NU + NI) * DM;
    for (int i = blockIdx.x * blockDim.x + threadIdx.x; i < total; i += gridDim.x * blockDim.x) {
        float v;
        if (i < NE * DM)                   v = ee[i];
        else if (i < (NE + NU) * DM)       v = ue[i - NE * DM];
        else if (i < (NE + 2 * NU) * DM)   v = cf[i - (NE + NU) * DM];
        else                               v = cf[NU * DM + (i - (NE + 2 * NU) * DM)];
        out[i] = v;
    }
}

__global__ void k_zero() {
    for (int i = blockIdx.x * blockDim.x + threadIdx.x; i < SCAN_NBLK * SCAN_BLK;
         i += gridDim.x * blockDim.x) {
        g_cnt[i] = 0;
        if (i < NSEG) g_cur[i] = 0;
    }
}

__global__ void k_count(const int* __restrict__ heads, const int* __restrict__ imat) {
    for (int i = blockIdx.x * blockDim.x + threadIdx.x; i < NEDGE; i += gridDim.x * blockDim.x) {
        atomicAdd(&g_cnt[heads[i]], 1);
        atomicAdd(&g_cnt[SEG_U + imat[2 * i]], 1);
        atomicAdd(&g_cnt[SEG_I + imat[2 * i + 1]], 1);
    }
}

__global__ void k_scan1() {
    __shared__ int sh[SCAN_BLK];
    int t = threadIdx.x;
    int i = blockIdx.x * SCAN_BLK + t;
    sh[t] = (i < SCAN_N) ? g_cnt[i] : 0;
    __syncthreads();
    for (int s = SCAN_BLK / 2; s > 0; s >>= 1) {
        if (t < s) sh[t] += sh[t + s];
        __syncthreads();
    }
    if (t == 0) g_bsum[blockIdx.x] = sh[0];
}
__global__ void k_scan2() {
    __shared__ int sh[SCAN_BLK];
    int t = threadIdx.x;
    int v = (t < SCAN_NBLK) ? g_bsum[t] : 0;
    sh[t] = v;
    __syncthreads();
    for (int d = 1; d < SCAN_BLK; d <<= 1) {
        int x = (t >= d) ? sh[t - d] : 0;
        __syncthreads();
        sh[t] += x;
        __syncthreads();
    }
    if (t < SCAN_NBLK) g_boff[t] = sh[t] - v;
}
__global__ void k_scan3() {
    __shared__ int sh[SCAN_BLK];
    int t = threadIdx.x;
    int i = blockIdx.x * SCAN_BLK + t;
    int v = (i < SCAN_N) ? g_cnt[i] : 0;
    sh[t] = v;
    __syncthreads();
    for (int d = 1; d < SCAN_BLK; d <<= 1) {
        int x = (t >= d) ? sh[t - d] : 0;
        __syncthreads();
        sh[t] += x;
        __syncthreads();
    }
    if (i < SCAN_N) g_off[i] = g_boff[blockIdx.x] + sh[t] - v;
}

// store PAYLOADS into perm:
//   entity positions: (tail << 5) | type
//   user positions:   col
//   item positions:   row
__global__ void k_scatter(const int* __restrict__ heads, const int* __restrict__ tails,
                          const int* __restrict__ etype, const int* __restrict__ imat) {
    for (int i = blockIdx.x * blockDim.x + threadIdx.x; i < NEDGE; i += gridDim.x * blockDim.x) {
        int h = heads[i];
        int p = g_off[h] + atomicAdd(&g_cur[h], 1);
        g_perm[p] = (tails[i] << 5) | etype[i];
        int row = imat[2 * i], col = imat[2 * i + 1];
        int r = SEG_U + row;
        p = g_off[r] + atomicAdd(&g_cur[r], 1);
        g_perm[p] = col;
        int c = SEG_I + col;
        p = g_off[c] + atomicAdd(&g_cur[c], 1);
        g_perm[p] = row;
    }
}

// entity aggregation: 16-lane groups x float4, 2 edges in flight;
// matvec via smem-transposed vectors (LDS broadcast).
__global__ void __launch_bounds__(256) k_entity(
        const float* __restrict__ ext_ent, int hop,
        const float* __restrict__ relw,
        const float* __restrict__ W1, const float* __restrict__ b1,
        const float* __restrict__ W2, const float* __restrict__ b2,
        float* __restrict__ out) {
    __shared__ float s_rel[NR * DM];          // 8 KB
    __shared__ float sW1[DM * 65];            // 16.25 KB
    __shared__ float sW2[DM * 65];            // 16.25 KB
    __shared__ float sb1[DM], sb2[DM];
    __shared__ float sA1[8 * 64], sA2[8 * 64]; // 4 KB scratch (per-warp vectors)
    int t = threadIdx.x;
    for (int i = t; i < NR * DM; i += blockDim.x) s_rel[i] = relw[i];
    for (int i = t; i < DM * DM; i += blockDim.x) {
        int d = i >> 6, k = i & 63;
        sW1[d * 65 + k] = W1[i];
        sW2[d * 65 + k] = W2[i];
    }
    if (t < DM) { sb1[t] = b1[t]; sb2[t] = b2[t]; }
    __syncthreads();

    const float4* entin4 = (const float4*)(hop ? g_entB : ext_ent);
    const float4* srel4  = (const float4*)s_rel;
    float* entout        = hop ? g_entA : g_entB;

    int lane = t & 31, w = t >> 5;
    int gg = lane >> 4, li = lane & 15;
    int e = blockIdx.x * 8 + w;
    if (e >= NE) return;
    int p0 = g_off[e], p1 = g_off[e + 1];
    int n = p1 - p0;
    bool eItem = e < NI;

    float4 A1 = make_float4(0,0,0,0), A2 = make_float4(0,0,0,0), AR = make_float4(0,0,0,0);
    int nc = 0;
    for (int p = p0 + gg; p < p1; p += 2) {
        int packed = g_perm[p];
        int tl = packed >> 5, ty = packed & 31;
        float4 r  = srel4[ty * 16 + li];
        float4 tv = entin4[tl * 16 + li];
        if (eItem != (tl < NI)) {
            A1.x += tv.x * r.x; A1.y += tv.y * r.y; A1.z += tv.z * r.z; A1.w += tv.w * r.w;
            nc++;
        } else {
            A2.x += tv.x + r.x; A2.y += tv.y + r.y; A2.z += tv.z + r.z; A2.w += tv.w + r.w;
        }
        AR.x += r.x; AR.y += r.y; AR.z += r.z; AR.w += r.w;
    }
    // reduce the 2 groups
    A1.x += __shfl_xor_sync(0xffffffffu, A1.x, 16);
    A1.y += __shfl_xor_sync(0xffffffffu, A1.y, 16);
    A1.z += __shfl_xor_sync(0xffffffffu, A1.z, 16);
    A1.w += __shfl_xor_sync(0xffffffffu, A1.w, 16);
    A2.x += __shfl_xor_sync(0xffffffffu, A2.x, 16);
    A2.y += __shfl_xor_sync(0xffffffffu, A2.y, 16);
    A2.z += __shfl_xor_sync(0xffffffffu, A2.z, 16);
    A2.w += __shfl_xor_sync(0xffffffffu, A2.w, 16);
    AR.x += __shfl_xor_sync(0xffffffffu, AR.x, 16);
    AR.y += __shfl_xor_sync(0xffffffffu, AR.y, 16);
    AR.z += __shfl_xor_sync(0xffffffffu, AR.z, 16);
    AR.w += __shfl_xor_sync(0xffffffffu, AR.w, 16);
    nc   += __shfl_xor_sync(0xffffffffu, nc, 16);

    float i1 = 1.f / fmaxf((float)nc, 1.f);
    float i2 = 1.f / fmaxf((float)(n - nc), 1.f);
    A1.x *= i1; A1.y *= i1; A1.z *= i1; A1.w *= i1;
    A2.x *= i2; A2.y *= i2; A2.z *= i2; A2.w *= i2;
    if (gg == 0) {
        *(float4*)&sA1[w * 64 + 4 * li] = A1;
        *(float4*)&sA2[w * 64 + 4 * li] = A2;
        if (eItem) {
            float dn = 1.f / fmaxf((float)n, 1.f);
            float4 rr = make_float4(AR.x * dn, AR.y * dn, AR.z * dn, AR.w * dn);
            ((float4*)g_rel)[e * 16 + li] = rr;
        }
    }
    __syncwarp();

    // matvec: lane = output dims (lane, lane+32); a broadcast from smem
    const float* av1 = &sA1[w * 64];
    const float* av2 = &sA2[w * 64];
    float o10 = sb1[lane], o11 = sb1[lane + 32];
    float o20 = sb2[lane], o21 = sb2[lane + 32];
    #pragma unroll
    for (int k = 0; k < 64; k++) {
        float a1k = av1[k], a2k = av2[k];
        o10 += a1k * sW1[lane * 65 + k];
        o11 += a1k * sW1[(lane + 32) * 65 + k];
        o20 += a2k * sW2[lane * 65 + k];
        o21 += a2k * sW2[(lane + 32) * 65 + k];
    }
    float v0 = 0.5f * (lrelu(o10) + lrelu(o20));
    float v1 = 0.5f * (lrelu(o11) + lrelu(o21));
    float ss = warpsum(v0 * v0 + v1 * v1);
    float inv = 1.f / fmaxf(sqrtf(ss), 1e-12f);
    v0 *= inv; v1 *= inv;
    entout[e * 64 + lane] = v0;
    entout[e * 64 + 32 + lane] = v1;
    out[e * 64 + lane] += v0;
    out[e * 64 + 32 + lane] += v1;
}

__global__ void k_relkg(const float* __restrict__ ext_ent, int hop) {
    const float* kgbase = hop ? g_entB : ext_ent;
    int i = blockIdx.x * blockDim.x + threadIdx.x;
    if (i < NI * DM) g_relkg[i] = g_rel[i] * kgbase[i];
}

// item aggregation: 16-lane groups x float4, 2 rows in flight
__global__ void __launch_bounds__(256) k_item(
        const float* __restrict__ ext_ucf, int hop, float* __restrict__ out) {
    const float4* ucfin4 = (const float4*)(hop ? g_ucf0 : ext_ucf);
    float4* icfout4      = (float4*)(hop ? g_icf1 : g_icf0);
    float4* out4         = (float4*)out;
    int t = threadIdx.x, lane = t & 31;
    int gg = lane >> 4, li = lane & 15;
    int c = blockIdx.x * 8 + (t >> 5);
    if (c >= NI) return;
    int p0 = g_off[SEG_I + c], p1 = g_off[SEG_I + c + 1];
    int n = p1 - p0;
    float4 acc = make_float4(0,0,0,0);
    for (int p = p0 + gg; p < p1; p += 2) {
        int row = g_perm[p];
        float4 v = ucfin4[row * 16 + li];
        acc.x += v.x; acc.y += v.y; acc.z += v.z; acc.w += v.w;
    }
    acc.x += __shfl_xor_sync(0xffffffffu, acc.x, 16);
    acc.y += __shfl_xor_sync(0xffffffffu, acc.y, 16);
    acc.z += __shfl_xor_sync(0xffffffffu, acc.z, 16);
    acc.w += __shfl_xor_sync(0xffffffffu, acc.w, 16);
    float dn = 1.f / fmaxf((float)n, 1.f);
    acc.x *= dn; acc.y *= dn; acc.z *= dn; acc.w *= dn;
    float ss = warpsum(acc.x*acc.x + acc.y*acc.y + acc.z*acc.z + acc.w*acc.w) * 0.5f;
    float inv = 1.f / fmaxf(sqrtf(ss), 1e-12f);
    acc.x *= inv; acc.y *= inv; acc.z *= inv; acc.w *= inv;
    if (gg == 0) {
        icfout4[c * 16 + li] = acc;
        int ob = (NE + 2 * NU) * 16 + c * 16 + li;
        float4 o = out4[ob];
        o.x += acc.x; o.y += acc.y; o.z += acc.z; o.w += acc.w;
        out4[ob] = o;
    }
}

// fused user kernel: warp/user; pass1 oct-parallel (4 pairs), pass3 2-wide float4,
// smem state, max-free softmax, payload perm (col direct).
__global__ void __launch_bounds__(256) k_userhop(
        const float* __restrict__ ext_user, const float* __restrict__ ext_ucf,
        const float* __restrict__ ext_ent, const float* __restrict__ ext_icf,
        int hop, float* __restrict__ out)
{
    __shared__ __align__(16) float sm[8 * 320];   // per warp: U64|UC64|W64|WC64|COL64

    const float* kg   = hop ? g_entB : ext_ent;
    const float* icf  = hop ? g_icf0 : ext_icf;
    const float4* kg4  = (const float4*)kg;
    const float4* rk4  = (const float4*)g_relkg;
    const float4* icf4 = (const float4*)icf;
    const float2* rk2  = (const float2*)g_relkg;
    const float2* icf2 = (const float2*)icf;
    const float* usrc   = hop ? g_u    : ext_user;
    const float* ucfsrc = hop ? g_ucf0 : ext_ucf;
    float4* udst4   = (float4*)g_u;
    float4* ucfdst4 = (float4*)(hop ? g_ucf1 : g_ucf0);
    float2* udst2   = (float2*)g_u;
    float2* ucfdst2 = (float2*)(hop ? g_ucf1 : g_ucf0);
    float4* out4    = (float4*)out;

    int w = threadIdx.x >> 5, lane = threadIdx.x & 31;
    int u = blockIdx.x * 8 + w;
    if (u >= NU) return;

    float* sU  = sm + w * 320;
    float* sUC = sU + 64;
    float* sW  = sU + 128;
    float* sWC = sU + 192;
    int*   sCol = (int*)(sU + 256);

    int p0 = g_off[SEG_U + u];
    int n  = g_off[SEG_U + u + 1] - p0;
    if (n == 0) {
        float2 z = make_float2(0.f, 0.f);
        udst2[u * 32 + lane] = z;
        ucfdst2[u * 32 + lane] = z;
        return;
    }
    int pb = p0 - NEDGE;
    int nin = n < 64 ? n : 64;

    sU[lane]       = usrc[u * 64 + lane];
    sU[32 + lane]  = usrc[u * 64 + 32 + lane];
    sUC[lane]      = ucfsrc[u * 64 + lane];
    sUC[32 + lane] = ucfsrc[u * 64 + 32 + lane];
    if (lane < nin)      sCol[lane]      = g_perm[p0 + lane];        // payload = col
    if (lane + 32 < nin) sCol[lane + 32] = g_perm[p0 + lane + 32];
    __syncwarp();

    int li8 = lane & 7, g8 = lane >> 3;    // pass-1 groups (8 lanes, 4 pairs)
    int gg = lane >> 4, li = lane & 15;    // pass-3 groups (16 lanes, 2 pairs)
    float4 FA, FB;                         // final vectors (float4 layout)

    for (int it = 0; it < 3; it++) {
        // ---- pass 1: dots, 4 pairs concurrently ----
        for (int jb = 0; jb < nin; jb += 4) {
            int j = jb + g8;
            bool act = j < nin;
            int col = act ? sCol[j] : 0;
            float4 a0 = rk4[col * 16 + li8],  a1 = rk4[col * 16 + 8 + li8];
            float4 b0 = icf4[col * 16 + li8], b1 = icf4[col * 16 + 8 + li8];
            float4 u0 = *(const float4*)(sU + 4 * li8);
            float4 u1 = *(const float4*)(sU + 32 + 4 * li8);
            float4 c0 = *(const float4*)(sUC + 4 * li8);
            float4 c1 = *(const float4*)(sUC + 32 + 4 * li8);
            float s  = a0.x*u0.x + a0.y*u0.y + a0.z*u0.z + a0.w*u0.w
                     + a1.x*u1.x + a1.y*u1.y + a1.z*u1.z + a1.w*u1.w;
            float sc = b0.x*c0.x + b0.y*c0.y + b0.z*c0.z + b0.w*c0.w
                     + b1.x*c1.x + b1.y*c1.y + b1.z*c1.z + b1.w*c1.w;
            s  += __shfl_xor_sync(0xffffffffu, s, 1);
            sc += __shfl_xor_sync(0xffffffffu, sc, 1);
            s  += __shfl_xor_sync(0xffffffffu, s, 2);
            sc += __shfl_xor_sync(0xffffffffu, sc, 2);
            s  += __shfl_xor_sync(0xffffffffu, s, 4);
            sc += __shfl_xor_sync(0xffffffffu, sc, 4);
            if (li8 == 0 && act) { sW[j] = s; sWC[j] = sc; }
        }
        for (int j = 64; j < n; j++) {   // fallback (not taken for this data)
            int col = g_perm[p0 + j];
            float2 rk = rk2[col * 32 + lane];
            float2 iv = icf2[col * 32 + lane];
            float s  = warpsum(rk.x * sU[2 * lane] + rk.y * sU[2 * lane + 1]);
            float sc = warpsum(iv.x * sUC[2 * lane] + iv.y * sUC[2 * lane + 1]);
            if (lane == 0) { g_p[pb + j] = s; g_pcf[pb + j] = sc; }
        }
        __syncwarp();
        // ---- pass 2: weights = exp(sigmoid(dot)) (max-free, exact) ----
        float se = 0.f, sec = 0.f;
        if (lane < nin) {
            float e  = __expf(sigmoidf(sW[lane]));
            float ec = __expf(sigmoidf(sWC[lane]));
            sW[lane] = e; sWC[lane] = ec; se += e; sec += ec;
        }
        if (lane + 32 < nin) {
            float e  = __expf(sigmoidf(sW[lane + 32]));
            float ec = __expf(sigmoidf(sWC[lane + 32]));
            sW[lane + 32] = e; sWC[lane + 32] = ec; se += e; sec += ec;
        }
        for (int j = 64 + lane; j < n; j += 32) {
            float e  = __expf(sigmoidf(g_p[pb + j]));
            float ec = __expf(sigmoidf(g_pcf[pb + j]));
            g_p[pb + j] = e; g_pcf[pb + j] = ec;
            se += e; sec += ec;
        }
        se = warpsum(se); sec = warpsum(sec);
        float inv = 1.f / se, invc = 1.f / sec;
        __syncwarp();
        // ---- pass 3: weighted accumulation, 2 pairs in flight, float4 ----
        float4 A = make_float4(0,0,0,0), B = make_float4(0,0,0,0);
        for (int j = gg; j < nin; j += 2) {
            int col = sCol[j];
            float wp = sW[j] * inv, wc = sWC[j] * invc;
            float4 gv = kg4[col * 16 + li];
            float4 iv = icf4[col * 16 + li];
            A.x += wp * gv.x; A.y += wp * gv.y; A.z += wp * gv.z; A.w += wp * gv.w;
            B.x += wc * iv.x; B.y += wc * iv.y; B.z += wc * iv.z; B.w += wc * iv.w;
        }
        if (gg == 0) {
            for (int j = 64; j < n; j++) {
                float wp = g_p[pb + j] * inv, wc = g_pcf[pb + j] * invc;
                int col = g_perm[p0 + j];
                float4 gv = kg4[col * 16 + li];
                float4 iv = icf4[col * 16 + li];
                A.x += wp * gv.x; A.y += wp * gv.y; A.z += wp * gv.z; A.w += wp * gv.w;
                B.x += wc * iv.x; B.y += wc * iv.y; B.z += wc * iv.z; B.w += wc * iv.w;
            }
        }
        A.x += __shfl_xor_sync(0xffffffffu, A.x, 16);
        A.y += __shfl_xor_sync(0xffffffffu, A.y, 16);
        A.z += __shfl_xor_sync(0xffffffffu, A.z, 16);
        A.w += __shfl_xor_sync(0xffffffffu, A.w, 16);
        B.x += __shfl_xor_sync(0xffffffffu, B.x, 16);
        B.y += __shfl_xor_sync(0xffffffffu, B.y, 16);
        B.z += __shfl_xor_sync(0xffffffffu, B.z, 16);
        B.w += __shfl_xor_sync(0xffffffffu, B.w, 16);
        float ss = warpsum(A.x*A.x + A.y*A.y + A.z*A.z + A.w*A.w) * 0.5f;
        float i1 = 1.f / fmaxf(sqrtf(ss), 1e-12f);
        ss = warpsum(B.x*B.x + B.y*B.y + B.z*B.z + B.w*B.w) * 0.5f;
        float i2 = 1.f / fmaxf(sqrtf(ss), 1e-12f);
        FA = make_float4(A.x*i1, A.y*i1, A.z*i1, A.w*i1);
        FB = make_float4(B.x*i2, B.y*i2, B.z*i2, B.w*i2);
        if (it < 2) {
            __syncwarp();
            if (gg == 0) {
                *(float4*)(sU + 4 * li)  = FA;
                *(float4*)(sUC + 4 * li) = FB;
            }
            __syncwarp();
        }
    }

    if (gg == 0) {
        udst4[u * 16 + li] = FA;
        ucfdst4[u * 16 + li] = FB;
        int o1 = NE * 16 + u * 16 + li;
        float4 o = out4[o1];
        o.x += FA.x; o.y += FA.y; o.z += FA.z; o.w += FA.w;
        out4[o1] = o;
        int o2 = (NE + NU) * 16 + u * 16 + li;
        o = out4[o2];
        o.x += FB.x; o.y += FB.y; o.z += FB.z; o.w += FB.w;
        out4[o2] = o;
    }
}

extern "C" void kernel_launch(void* const* d_in, const int* in_sizes, int n_in,
                              void* d_out, int out_size) {
    const float* user_emb = (const float*)d_in[0];
    const float* entity_emb = (const float*)d_in[1];
    const float* emb_cf = (const float*)d_in[2];
    const float* relw = (const float*)d_in[3];
    const float* W1 = (const float*)d_in[4];
    const float* B1 = (const float*)d_in[5];
    const float* W2 = (const float*)d_in[6];
    const float* B2 = (const float*)d_in[7];
    const int* eidx = (const int*)d_in[8];
    const int* etype = (const int*)d_in[9];
    const int* imat = (const int*)d_in[10];
    float* out = (float*)d_out;

    const int* heads = eidx;
    const int* tails = eidx + NEDGE;
    const float* ucf_ext = emb_cf;
    const float* icf_ext = emb_cf + NU * DM;

    k_init<<<2048, 256>>>(user_emb, entity_emb, emb_cf, out);
    k_zero<<<1056, 256>>>();
    k_count<<<3907, 256>>>(heads, imat);
    k_scan1<<<SCAN_NBLK, SCAN_BLK>>>();
    k_scan2<<<1, SCAN_BLK>>>();
    k_scan3<<<SCAN_NBLK, SCAN_BLK>>>();
    k_scatter<<<3907, 256>>>(heads, tails, etype, imat);

    for (int h = 0; h < 2; h++) {
        k_entity<<<NE / 8, 256>>>(entity_emb, h, relw,
                                  W1 + h * DM * DM, B1 + h * DM,
                                  W2 + h * DM * DM, B2 + h * DM, out);
        k_relkg<<<(NI * DM + 255) / 256, 256>>>(entity_emb, h);
        k_item<<<NI / 8, 256>>>(ucf_ext, h, out);
        k_userhop<<<(NU + 7) / 8, 256>>>(user_emb, ucf_ext, entity_emb, icf_ext,
                                         h, out);
    }
    (void)in_sizes; (void)n_in; (void)out_size;
}

// round 7
// speedup vs baseline: 1.4435x; 1.4435x over previous
#include <cuda_runtime.h>
#include <math.h>

#define NU 100000
#define NI 50000
#define NE 120000
#define NR 32
#define DM 64
#define NEDGE 1000000
#define NCF 1000000

#define SEG_U 120000
#define SEG_I 220000
#define NSEG 270000
#define SCAN_N 270001
#define SCAN_BLK 1024
#define SCAN_NBLK 264

__device__ int   g_cnt[SCAN_NBLK * SCAN_BLK];
__device__ int   g_off[SCAN_NBLK * SCAN_BLK + 1];
__device__ int   g_cur[NSEG];
__device__ int   g_perm[NEDGE + 2 * NCF];   // PAYLOADS: entity=(tail<<5)|type, user=col, item=row
__device__ int   g_bsum[SCAN_BLK];
__device__ int   g_boff[SCAN_BLK];

__device__ float g_entA[NE * DM];
__device__ float g_entB[NE * DM];
__device__ float g_rel[NI * DM];
__device__ float g_relkg[NI * DM];
__device__ float g_u[NU * DM];
__device__ float g_ucf0[NU * DM];
__device__ float g_ucf1[NU * DM];
__device__ float g_icf0[NI * DM];
__device__ float g_icf1[NI * DM];
__device__ float g_p[NCF];
__device__ float g_pcf[NCF];

__device__ __forceinline__ float warpsum(float v) {
    #pragma unroll
    for (int o = 16; o; o >>= 1) v += __shfl_xor_sync(0xffffffffu, v, o);
    return v;
}
__device__ __forceinline__ float lrelu(float x) { return x > 0.f ? x : 0.01f * x; }
__device__ __forceinline__ float sigmoidf(float x) { return 1.f / (1.f + __expf(-x)); }

__global__ void k_init(const float* __restrict__ ue, const float* __restrict__ ee,
                       const float* __restrict__ cf, float* __restrict__ out) {
    const int total = (NE + NU + NU + NI) * DM;
    for (int i = blockIdx.x * blockDim.x + threadIdx.x; i < total; i += gridDim.x * blockDim.x) {
        float v;
        if (i < NE * DM)                   v = ee[i];
        else if (i < (NE + NU) * DM)       v = ue[i - NE * DM];
        else if (i < (NE + 2 * NU) * DM)   v = cf[i - (NE + NU) * DM];
        else                               v = cf[NU * DM + (i - (NE + 2 * NU) * DM)];
        out[i] = v;
    }
}

__global__ void k_zero() {
    for (int i = blockIdx.x * blockDim.x + threadIdx.x; i < SCAN_NBLK * SCAN_BLK;
         i += gridDim.x * blockDim.x) {
        g_cnt[i] = 0;
        if (i < NSEG) g_cur[i] = 0;
    }
}

__global__ void k_count(const int* __restrict__ heads, const int* __restrict__ imat) {
    for (int i = blockIdx.x * blockDim.x + threadIdx.x; i < NEDGE; i += gridDim.x * blockDim.x) {
        atomicAdd(&g_cnt[heads[i]], 1);
        atomicAdd(&g_cnt[SEG_U + imat[2 * i]], 1);
        atomicAdd(&g_cnt[SEG_I + imat[2 * i + 1]], 1);
    }
}

__global__ void k_scan1() {
    __shared__ int sh[SCAN_BLK];
    int t = threadIdx.x;
    int i = blockIdx.x * SCAN_BLK + t;
    sh[t] = (i < SCAN_N) ? g_cnt[i] : 0;
    __syncthreads();
    for (int s = SCAN_BLK / 2; s > 0; s >>= 1) {
        if (t < s) sh[t] += sh[t + s];
        __syncthreads();
    }
    if (t == 0) g_bsum[blockIdx.x] = sh[0];
}
__global__ void k_scan2() {
    __shared__ int sh[SCAN_BLK];
    int t = threadIdx.x;
    int v = (t < SCAN_NBLK) ? g_bsum[t] : 0;
    sh[t] = v;
    __syncthreads();
    for (int d = 1; d < SCAN_BLK; d <<= 1) {
        int x = (t >= d) ? sh[t - d] : 0;
        __syncthreads();
        sh[t] += x;
        __syncthreads();
    }
    if (t < SCAN_NBLK) g_boff[t] = sh[t] - v;
}
__global__ void k_scan3() {
    __shared__ int sh[SCAN_BLK];
    int t = threadIdx.x;
    int i = blockIdx.x * SCAN_BLK + t;
    int v = (i < SCAN_N) ? g_cnt[i] : 0;
    sh[t] = v;
    __syncthreads();
    for (int d = 1; d < SCAN_BLK; d <<= 1) {
        int x = (t >= d) ? sh[t - d] : 0;
        __syncthreads();
        sh[t] += x;
        __syncthreads();
    }
    if (i < SCAN_N) g_off[i] = g_boff[blockIdx.x] + sh[t] - v;
}

// store PAYLOADS into perm (kills one indirection level in all consumers)
__global__ void k_scatter(const int* __restrict__ heads, const int* __restrict__ tails,
                          const int* __restrict__ etype, const int* __restrict__ imat) {
    for (int i = blockIdx.x * blockDim.x + threadIdx.x; i < NEDGE; i += gridDim.x * blockDim.x) {
        int h = heads[i];
        int p = g_off[h] + atomicAdd(&g_cur[h], 1);
        g_perm[p] = (tails[i] << 5) | etype[i];
        int row = imat[2 * i], col = imat[2 * i + 1];
        int r = SEG_U + row;
        p = g_off[r] + atomicAdd(&g_cur[r], 1);
        g_perm[p] = col;
        int c = SEG_I + col;
        p = g_off[c] + atomicAdd(&g_cur[c], 1);
        g_perm[p] = row;
    }
}

// entity aggregation (R5-proven warp-per-entity shape, payload perm)
__global__ void k_entity(const float* __restrict__ ext_ent, int hop,
                         const float* __restrict__ relw,
                         const float* __restrict__ W1, const float* __restrict__ b1,
                         const float* __restrict__ W2, const float* __restrict__ b2,
                         float* __restrict__ out) {
    __shared__ float s_rel[NR * DM];
    __shared__ float sW1[DM * 65];
    __shared__ float sW2[DM * 65];
    __shared__ float sb1[DM], sb2[DM];
    int t = threadIdx.x;
    for (int i = t; i < NR * DM; i += blockDim.x) s_rel[i] = relw[i];
    for (int i = t; i < DM * DM; i += blockDim.x) {
        int d = i >> 6, k = i & 63;
        sW1[d * 65 + k] = W1[i];
        sW2[d * 65 + k] = W2[i];
    }
    if (t < DM) { sb1[t] = b1[t]; sb2[t] = b2[t]; }
    __syncthreads();

    const float* entin = hop ? g_entB : ext_ent;
    float* entout      = hop ? g_entA : g_entB;

    int lane = t & 31;
    int e = blockIdx.x * (blockDim.x >> 5) + (t >> 5);
    if (e >= NE) return;
    int p0 = g_off[e], p1 = g_off[e + 1];
    bool eItem = e < NI;

    float a10 = 0, a11 = 0, a20 = 0, a21 = 0, ar0 = 0, ar1 = 0;
    int nc = 0;
    for (int p = p0; p < p1; p++) {
        int packed = g_perm[p];
        int tl = packed >> 5, ty = packed & 31;
        float r0 = s_rel[ty * 64 + lane], r1 = s_rel[ty * 64 + 32 + lane];
        float t0 = entin[tl * 64 + lane], t1 = entin[tl * 64 + 32 + lane];
        bool cross = eItem != (tl < NI);
        if (cross) { a10 += t0 * r0; a11 += t1 * r1; nc++; }
        else       { a20 += t0 + r0; a21 += t1 + r1; }
        ar0 += r0; ar1 += r1;
    }
    int n = p1 - p0;
    float i1 = 1.f / fmaxf((float)nc, 1.f);
    float i2 = 1.f / fmaxf((float)(n - nc), 1.f);
    a10 *= i1; a11 *= i1; a20 *= i2; a21 *= i2;

    float o10 = sb1[lane], o11 = sb1[lane + 32];
    float o20 = sb2[lane], o21 = sb2[lane + 32];
    #pragma unroll
    for (int k = 0; k < 64; k++) {
        float a = __shfl_sync(0xffffffffu, (k < 32) ? a10 : a11, k & 31);
        o10 += a * sW1[lane * 65 + k];
        o11 += a * sW1[(lane + 32) * 65 + k];
    }
    #pragma unroll
    for (int k = 0; k < 64; k++) {
        float a = __shfl_sync(0xffffffffu, (k < 32) ? a20 : a21, k & 31);
        o20 += a * sW2[lane * 65 + k];
        o21 += a * sW2[(lane + 32) * 65 + k];
    }
    float v0 = 0.5f * (lrelu(o10) + lrelu(o20));
    float v1 = 0.5f * (lrelu(o11) + lrelu(o21));
    float ss = warpsum(v0 * v0 + v1 * v1);
    float inv = 1.f / fmaxf(sqrtf(ss), 1e-12f);
    v0 *= inv; v1 *= inv;
    entout[e * 64 + lane] = v0;
    entout[e * 64 + 32 + lane] = v1;
    out[e * 64 + lane] += v0;
    out[e * 64 + 32 + lane] += v1;
    if (eItem) {
        float dn = 1.f / fmaxf((float)n, 1.f);
        g_rel[e * 64 + lane] = ar0 * dn;
        g_rel[e * 64 + 32 + lane] = ar1 * dn;
    }
}

__global__ void k_relkg(const float* __restrict__ ext_ent, int hop) {
    const float* kgbase = hop ? g_entB : ext_ent;
    int i = blockIdx.x * blockDim.x + threadIdx.x;
    if (i < NI * DM) g_relkg[i] = g_rel[i] * kgbase[i];
}

// item aggregation (R5 shape, payload perm)
__global__ void k_item(const float* __restrict__ ext_ucf, int hop,
                       float* __restrict__ out) {
    const float* ucfin = hop ? g_ucf0 : ext_ucf;
    float* icfout      = hop ? g_icf1 : g_icf0;
    int t = threadIdx.x, lane = t & 31;
    int c = blockIdx.x * (blockDim.x >> 5) + (t >> 5);
    if (c >= NI) return;
    int p0 = g_off[SEG_I + c], p1 = g_off[SEG_I + c + 1];
    float a0 = 0, a1 = 0;
    for (int p = p0; p < p1; p++) {
        int row = g_perm[p];
        a0 += ucfin[row * 64 + lane];
        a1 += ucfin[row * 64 + 32 + lane];
    }
    float dn = 1.f / fmaxf((float)(p1 - p0), 1.f);
    a0 *= dn; a1 *= dn;
    float ss = warpsum(a0 * a0 + a1 * a1);
    float inv = 1.f / fmaxf(sqrtf(ss), 1e-12f);
    a0 *= inv; a1 *= inv;
    icfout[c * 64 + lane] = a0;
    icfout[c * 64 + 32 + lane] = a1;
    const int ob = (NE + 2 * NU) * DM;
    out[ob + c * 64 + lane] += a0;
    out[ob + c * 64 + 32 + lane] += a1;
}

// fused user kernel (exact R5 structure; cols come straight from payload perm)
__global__ void __launch_bounds__(256) k_userhop(
        const float* __restrict__ ext_user, const float* __restrict__ ext_ucf,
        const float* __restrict__ ext_ent, const float* __restrict__ ext_icf,
        int hop, float* __restrict__ out)
{
    __shared__ __align__(16) float sm[8 * 320];   // per warp: U64|UC64|W64|WC64|COL64

    const float* kg   = hop ? g_entB : ext_ent;
    const float* icf  = hop ? g_icf0 : ext_icf;
    const float4* rk4  = (const float4*)g_relkg;
    const float4* icf4 = (const float4*)icf;
    const float2* kg2  = (const float2*)kg;
    const float2* icf2 = (const float2*)icf;
    const float2* rk2  = (const float2*)g_relkg;
    const float* usrc   = hop ? g_u    : ext_user;
    const float* ucfsrc = hop ? g_ucf0 : ext_ucf;
    float2* udst2   = (float2*)g_u;
    float2* ucfdst2 = (float2*)(hop ? g_ucf1 : g_ucf0);
    float2* out2    = (float2*)out;

    int w = threadIdx.x >> 5, lane = threadIdx.x & 31;
    int u = blockIdx.x * 8 + w;
    if (u >= NU) return;

    float* sU  = sm + w * 320;
    float* sUC = sU + 64;
    float* sW  = sU + 128;
    float* sWC = sU + 192;
    int*   sCol = (int*)(sU + 256);

    int p0 = g_off[SEG_U + u];
    int n  = g_off[SEG_U + u + 1] - p0;
    if (n == 0) {
        float2 z = make_float2(0.f, 0.f);
        udst2[u * 32 + lane] = z;
        ucfdst2[u * 32 + lane] = z;
        return;
    }
    int pb = p0 - NEDGE;
    int nin = n < 64 ? n : 64;

    sU[lane]       = usrc[u * 64 + lane];
    sU[32 + lane]  = usrc[u * 64 + 32 + lane];
    sUC[lane]      = ucfsrc[u * 64 + lane];
    sUC[32 + lane] = ucfsrc[u * 64 + 32 + lane];
    if (lane < nin)      sCol[lane]      = g_perm[p0 + lane];        // payload = col
    if (lane + 32 < nin) sCol[lane + 32] = g_perm[p0 + lane + 32];
    __syncwarp();

    float2 ud, cd;   // final result registers
    int li = lane & 7, g = lane >> 3;

    for (int it = 0; it < 3; it++) {
        // ---- pass 1: dots, 4 pairs per warp concurrently (8 lanes each) ----
        for (int jb = 0; jb < nin; jb += 4) {
            int j = jb + g;
            bool act = j < nin;
            int col = act ? sCol[j] : 0;
            float4 a0 = rk4[col * 16 + li],     a1 = rk4[col * 16 + 8 + li];
            float4 b0 = icf4[col * 16 + li],    b1 = icf4[col * 16 + 8 + li];
            float4 u0 = *(const float4*)(sU + 4 * li);
            float4 u1 = *(const float4*)(sU + 32 + 4 * li);
            float4 c0 = *(const float4*)(sUC + 4 * li);
            float4 c1 = *(const float4*)(sUC + 32 + 4 * li);
            float s  = a0.x*u0.x + a0.y*u0.y + a0.z*u0.z + a0.w*u0.w
                     + a1.x*u1.x + a1.y*u1.y + a1.z*u1.z + a1.w*u1.w;
            float sc = b0.x*c0.x + b0.y*c0.y + b0.z*c0.z + b0.w*c0.w
                     + b1.x*c1.x + b1.y*c1.y + b1.z*c1.z + b1.w*c1.w;
            s  += __shfl_xor_sync(0xffffffffu, s, 1);
            sc += __shfl_xor_sync(0xffffffffu, sc, 1);
            s  += __shfl_xor_sync(0xffffffffu, s, 2);
            sc += __shfl_xor_sync(0xffffffffu, sc, 2);
            s  += __shfl_xor_sync(0xffffffffu, s, 4);
            sc += __shfl_xor_sync(0xffffffffu, sc, 4);
            if (li == 0 && act) { sW[j] = s; sWC[j] = sc; }
        }
        for (int j = 64; j < n; j++) {   // fallback (not taken for this data)
            int col = g_perm[p0 + j];
            float2 rk = rk2[col * 32 + lane];
            float2 iv = icf2[col * 32 + lane];
            float s  = warpsum(rk.x * sU[2 * lane] + rk.y * sU[2 * lane + 1]);
            float sc = warpsum(iv.x * sUC[2 * lane] + iv.y * sUC[2 * lane + 1]);
            if (lane == 0) { g_p[pb + j] = s; g_pcf[pb + j] = sc; }
        }
        __syncwarp();
        // ---- pass 2: weights = exp(sigmoid(dot)) (max-free, exact) ----
        float se = 0.f, sec = 0.f;
        if (lane < nin) {
            float e  = __expf(sigmoidf(sW[lane]));
            float ec = __expf(sigmoidf(sWC[lane]));
            sW[lane] = e; sWC[lane] = ec; se += e; sec += ec;
        }
        if (lane + 32 < nin) {
            float e  = __expf(sigmoidf(sW[lane + 32]));
            float ec = __expf(sigmoidf(sWC[lane + 32]));
            sW[lane + 32] = e; sWC[lane + 32] = ec; se += e; sec += ec;
        }
        for (int j = 64 + lane; j < n; j += 32) {
            float e  = __expf(sigmoidf(g_p[pb + j]));
            float ec = __expf(sigmoidf(g_pcf[pb + j]));
            g_p[pb + j] = e; g_pcf[pb + j] = ec;
            se += e; sec += ec;
        }
        se = warpsum(se); sec = warpsum(sec);
        float inv = 1.f / se, invc = 1.f / sec;
        __syncwarp();
        // ---- pass 3: weighted accumulation ----
        float2 A = make_float2(0.f, 0.f), B = make_float2(0.f, 0.f);
        for (int j = 0; j < nin; j++) {
            int col = sCol[j];
            float wp = sW[j] * inv, wc = sWC[j] * invc;
            float2 gv = kg2[col * 32 + lane];
            float2 iv = icf2[col * 32 + lane];
            A.x += wp * gv.x; A.y += wp * gv.y;
            B.x += wc * iv.x; B.y += wc * iv.y;
        }
        for (int j = 64; j < n; j++) {
            float wp = g_p[pb + j] * inv, wc = g_pcf[pb + j] * invc;
            int col = g_perm[p0 + j];
            float2 gv = kg2[col * 32 + lane];
            float2 iv = icf2[col * 32 + lane];
            A.x += wp * gv.x; A.y += wp * gv.y;
            B.x += wc * iv.x; B.y += wc * iv.y;
        }
        float ss = warpsum(A.x * A.x + A.y * A.y);
        float i1 = 1.f / fmaxf(sqrtf(ss), 1e-12f);
        ss = warpsum(B.x * B.x + B.y * B.y);
        float i2 = 1.f / fmaxf(sqrtf(ss), 1e-12f);
        ud.x = A.x * i1; ud.y = A.y * i1;
        cd.x = B.x * i2; cd.y = B.y * i2;
        if (it < 2) {
            __syncwarp();
            sU[2 * lane] = ud.x;  sU[2 * lane + 1] = ud.y;
            sUC[2 * lane] = cd.x; sUC[2 * lane + 1] = cd.y;
            __syncwarp();
        }
    }

    udst2[u * 32 + lane] = ud;
    ucfdst2[u * 32 + lane] = cd;
    int o1 = NE * 32 + u * 32 + lane;
    float2 o = out2[o1]; o.x += ud.x; o.y += ud.y; out2[o1] = o;
    int o2 = (NE + NU) * 32 + u * 32 + lane;
    o = out2[o2]; o.x += cd.x; o.y += cd.y; out2[o2] = o;
}

extern "C" void kernel_launch(void* const* d_in, const int* in_sizes, int n_in,
                              void* d_out, int out_size) {
    const float* user_emb = (const float*)d_in[0];
    const float* entity_emb = (const float*)d_in[1];
    const float* emb_cf = (const float*)d_in[2];
    const float* relw = (const float*)d_in[3];
    const float* W1 = (const float*)d_in[4];
    const float* B1 = (const float*)d_in[5];
    const float* W2 = (const float*)d_in[6];
    const float* B2 = (const float*)d_in[7];
    const int* eidx = (const int*)d_in[8];
    const int* etype = (const int*)d_in[9];
    const int* imat = (const int*)d_in[10];
    float* out = (float*)d_out;

    const int* heads = eidx;
    const int* tails = eidx + NEDGE;
    const float* ucf_ext = emb_cf;
    const float* icf_ext = emb_cf + NU * DM;

    k_init<<<2048, 256>>>(user_emb, entity_emb, emb_cf, out);
    k_zero<<<1056, 256>>>();
    k_count<<<3907, 256>>>(heads, imat);
    k_scan1<<<SCAN_NBLK, SCAN_BLK>>>();
    k_scan2<<<1, SCAN_BLK>>>();
    k_scan3<<<SCAN_NBLK, SCAN_BLK>>>();
    k_scatter<<<3907, 256>>>(heads, tails, etype, imat);

    for (int h = 0; h < 2; h++) {
        k_entity<<<NE / 8, 256>>>(entity_emb, h, relw,
                                  W1 + h * DM * DM, B1 + h * DM,
                                  W2 + h * DM * DM, B2 + h * DM, out);
        k_relkg<<<(NI * DM + 255) / 256, 256>>>(entity_emb, h);
        k_item<<<NI / 8, 256>>>(ucf_ext, h, out);
        k_userhop<<<(NU + 7) / 8, 256>>>(user_emb, ucf_ext, entity_emb, icf_ext,
                                         h, out);
    }
    (void)in_sizes; (void)n_in; (void)out_size;
}

// round 8
// speedup vs baseline: 1.4698x; 1.0182x over previous
#include <cuda_runtime.h>
#include <math.h>

#define NU 100000
#define NI 50000
#define NE 120000
#define NR 32
#define DM 64
#define NEDGE 1000000
#define NCF 1000000

#define SEG_U 120000
#define SEG_I 220000
#define NSEG 270000
#define SCAN_N 270001
#define SCAN_BLK 1024
#define SCAN_NBLK 264

__device__ int   g_cnt[SCAN_NBLK * SCAN_BLK];
__device__ int   g_off[SCAN_NBLK * SCAN_BLK + 1];
__device__ int   g_cur[NSEG];
__device__ int   g_perm[NEDGE + 2 * NCF];   // PAYLOADS: entity=(tail<<5)|type, user=col, item=row
__device__ int   g_bsum[SCAN_BLK];
__device__ int   g_boff[SCAN_BLK];

__device__ float g_entA[NE * DM];
__device__ float g_entB[NE * DM];
__device__ float g_relkg[NI * DM];
__device__ float g_u[NU * DM];
__device__ float g_ucf0[NU * DM];
__device__ float g_ucf1[NU * DM];
__device__ float g_icf0[NI * DM];
__device__ float g_icf1[NI * DM];
__device__ float g_p[NCF];
__device__ float g_pcf[NCF];

__device__ __forceinline__ float warpsum(float v) {
    #pragma unroll
    for (int o = 16; o; o >>= 1) v += __shfl_xor_sync(0xffffffffu, v, o);
    return v;
}
__device__ __forceinline__ float lrelu(float x) { return x > 0.f ? x : 0.01f * x; }
__device__ __forceinline__ float sigmoidf(float x) { return 1.f / (1.f + __expf(-x)); }

// init: out = concat(entity, user, ucf, icf)  +  zero the counting arrays
__global__ void k_init(const float* __restrict__ ue, const float* __restrict__ ee,
                       const float* __restrict__ cf, float* __restrict__ out) {
    const int total = (NE + NU + NU + NI) * DM;
    for (int i = blockIdx.x * blockDim.x + threadIdx.x; i < total; i += gridDim.x * blockDim.x) {
        if (i < SCAN_NBLK * SCAN_BLK) {
            g_cnt[i] = 0;
            if (i < NSEG) g_cur[i] = 0;
        }
        float v;
        if (i < NE * DM)                   v = ee[i];
        else if (i < (NE + NU) * DM)       v = ue[i - NE * DM];
        else if (i < (NE + 2 * NU) * DM)   v = cf[i - (NE + NU) * DM];
        else                               v = cf[NU * DM + (i - (NE + 2 * NU) * DM)];
        out[i] = v;
    }
}

__global__ void k_count(const int* __restrict__ heads, const int* __restrict__ imat) {
    for (int i = blockIdx.x * blockDim.x + threadIdx.x; i < NEDGE; i += gridDim.x * blockDim.x) {
        atomicAdd(&g_cnt[heads[i]], 1);
        atomicAdd(&g_cnt[SEG_U + imat[2 * i]], 1);
        atomicAdd(&g_cnt[SEG_I + imat[2 * i + 1]], 1);
    }
}

__global__ void k_scan1() {
    __shared__ int sh[SCAN_BLK];
    int t = threadIdx.x;
    int i = blockIdx.x * SCAN_BLK + t;
    sh[t] = (i < SCAN_N) ? g_cnt[i] : 0;
    __syncthreads();
    for (int s = SCAN_BLK / 2; s > 0; s >>= 1) {
        if (t < s) sh[t] += sh[t + s];
        __syncthreads();
    }
    if (t == 0) g_bsum[blockIdx.x] = sh[0];
}
__global__ void k_scan2() {
    __shared__ int sh[SCAN_BLK];
    int t = threadIdx.x;
    int v = (t < SCAN_NBLK) ? g_bsum[t] : 0;
    sh[t] = v;
    __syncthreads();
    for (int d = 1; d < SCAN_BLK; d <<= 1) {
        int x = (t >= d) ? sh[t - d] : 0;
        __syncthreads();
        sh[t] += x;
        __syncthreads();
    }
    if (t < SCAN_NBLK) g_boff[t] = sh[t] - v;
}
__global__ void k_scan3() {
    __shared__ int sh[SCAN_BLK];
    int t = threadIdx.x;
    int i = blockIdx.x * SCAN_BLK + t;
    int v = (i < SCAN_N) ? g_cnt[i] : 0;
    sh[t] = v;
    __syncthreads();
    for (int d = 1; d < SCAN_BLK; d <<= 1) {
        int x = (t >= d) ? sh[t - d] : 0;
        __syncthreads();
        sh[t] += x;
        __syncthreads();
    }
    if (i < SCAN_N) g_off[i] = g_boff[blockIdx.x] + sh[t] - v;
}

// store PAYLOADS into perm (kills one indirection level in all consumers)
__global__ void k_scatter(const int* __restrict__ heads, const int* __restrict__ tails,
                          const int* __restrict__ etype, const int* __restrict__ imat) {
    for (int i = blockIdx.x * blockDim.x + threadIdx.x; i < NEDGE; i += gridDim.x * blockDim.x) {
        int h = heads[i];
        int p = g_off[h] + atomicAdd(&g_cur[h], 1);
        g_perm[p] = (tails[i] << 5) | etype[i];
        int row = imat[2 * i], col = imat[2 * i + 1];
        int r = SEG_U + row;
        p = g_off[r] + atomicAdd(&g_cur[r], 1);
        g_perm[p] = col;
        int c = SEG_I + col;
        p = g_off[c] + atomicAdd(&g_cur[c], 1);
        g_perm[p] = row;
    }
}

// entity aggregation (warp-per-entity) + fused relkg production:
// relkg[e] = (mean rel over e's edges) * entin[e]  (items only)
__global__ void k_entity(const float* __restrict__ ext_ent, int hop,
                         const float* __restrict__ relw,
                         const float* __restrict__ W1, const float* __restrict__ b1,
                         const float* __restrict__ W2, const float* __restrict__ b2,
                         float* __restrict__ out) {
    __shared__ float s_rel[NR * DM];
    __shared__ float sW1[DM * 65];
    __shared__ float sW2[DM * 65];
    __shared__ float sb1[DM], sb2[DM];
    int t = threadIdx.x;
    for (int i = t; i < NR * DM; i += blockDim.x) s_rel[i] = relw[i];
    for (int i = t; i < DM * DM; i += blockDim.x) {
        int d = i >> 6, k = i & 63;
        sW1[d * 65 + k] = W1[i];
        sW2[d * 65 + k] = W2[i];
    }
    if (t < DM) { sb1[t] = b1[t]; sb2[t] = b2[t]; }
    __syncthreads();

    const float* entin = hop ? g_entB : ext_ent;
    float* entout      = hop ? g_entA : g_entB;

    int lane = t & 31;
    int e = blockIdx.x * (blockDim.x >> 5) + (t >> 5);
    if (e >= NE) return;
    int p0 = g_off[e], p1 = g_off[e + 1];
    bool eItem = e < NI;

    float a10 = 0, a11 = 0, a20 = 0, a21 = 0, ar0 = 0, ar1 = 0;
    int nc = 0;
    for (int p = p0; p < p1; p++) {
        int packed = g_perm[p];
        int tl = packed >> 5, ty = packed & 31;
        float r0 = s_rel[ty * 64 + lane], r1 = s_rel[ty * 64 + 32 + lane];
        float t0 = entin[tl * 64 + lane], t1 = entin[tl * 64 + 32 + lane];
        bool cross = eItem != (tl < NI);
        if (cross) { a10 += t0 * r0; a11 += t1 * r1; nc++; }
        else       { a20 += t0 + r0; a21 += t1 + r1; }
        ar0 += r0; ar1 += r1;
    }
    int n = p1 - p0;

    // fused relkg: rel mean * own input row (items only)
    if (eItem) {
        float dn = 1.f / fmaxf((float)n, 1.f);
        g_relkg[e * 64 + lane]      = (ar0 * dn) * entin[e * 64 + lane];
        g_relkg[e * 64 + 32 + lane] = (ar1 * dn) * entin[e * 64 + 32 + lane];
    }

    float i1 = 1.f / fmaxf((float)nc, 1.f);
    float i2 = 1.f / fmaxf((float)(n - nc), 1.f);
    a10 *= i1; a11 *= i1; a20 *= i2; a21 *= i2;

    float o10 = sb1[lane], o11 = sb1[lane + 32];
    float o20 = sb2[lane], o21 = sb2[lane + 32];
    #pragma unroll
    for (int k = 0; k < 64; k++) {
        float a = __shfl_sync(0xffffffffu, (k < 32) ? a10 : a11, k & 31);
        o10 += a * sW1[lane * 65 + k];
        o11 += a * sW1[(lane + 32) * 65 + k];
    }
    #pragma unroll
    for (int k = 0; k < 64; k++) {
        float a = __shfl_sync(0xffffffffu, (k < 32) ? a20 : a21, k & 31);
        o20 += a * sW2[lane * 65 + k];
        o21 += a * sW2[(lane + 32) * 65 + k];
    }
    float v0 = 0.5f * (lrelu(o10) + lrelu(o20));
    float v1 = 0.5f * (lrelu(o11) + lrelu(o21));
    float ss = warpsum(v0 * v0 + v1 * v1);
    float inv = 1.f / fmaxf(sqrtf(ss), 1e-12f);
    v0 *= inv; v1 *= inv;
    entout[e * 64 + lane] = v0;
    entout[e * 64 + 32 + lane] = v1;
    out[e * 64 + lane] += v0;
    out[e * 64 + 32 + lane] += v1;
}

// item aggregation (float2 loads)
__global__ void k_item(const float* __restrict__ ext_ucf, int hop,
                       float* __restrict__ out) {
    const float2* ucfin2 = (const float2*)(hop ? g_ucf0 : ext_ucf);
    float2* icfout2      = (float2*)(hop ? g_icf1 : g_icf0);
    float2* out2         = (float2*)out;
    int t = threadIdx.x, lane = t & 31;
    int c = blockIdx.x * (blockDim.x >> 5) + (t >> 5);
    if (c >= NI) return;
    int p0 = g_off[SEG_I + c], p1 = g_off[SEG_I + c + 1];
    float2 acc = make_float2(0.f, 0.f);
    for (int p = p0; p < p1; p++) {
        int row = g_perm[p];
        float2 v = ucfin2[row * 32 + lane];
        acc.x += v.x; acc.y += v.y;
    }
    float dn = 1.f / fmaxf((float)(p1 - p0), 1.f);
    acc.x *= dn; acc.y *= dn;
    float ss = warpsum(acc.x * acc.x + acc.y * acc.y);
    float inv = 1.f / fmaxf(sqrtf(ss), 1e-12f);
    acc.x *= inv; acc.y *= inv;
    icfout2[c * 32 + lane] = acc;
    int ob = (NE + 2 * NU) * 32 + c * 32 + lane;
    float2 o = out2[ob];
    o.x += acc.x; o.y += acc.y;
    out2[ob] = o;
}

// fused user kernel (R5/R7-proven structure; payload perm)
__global__ void __launch_bounds__(256) k_userhop(
        const float* __restrict__ ext_user, const float* __restrict__ ext_ucf,
        const float* __restrict__ ext_ent, const float* __restrict__ ext_icf,
        int hop, float* __restrict__ out)
{
    __shared__ __align__(16) float sm[8 * 320];   // per warp: U64|UC64|W64|WC64|COL64

    const float* kg   = hop ? g_entB : ext_ent;
    const float* icf  = hop ? g_icf0 : ext_icf;
    const float4* rk4  = (const float4*)g_relkg;
    const float4* icf4 = (const float4*)icf;
    const float2* kg2  = (const float2*)kg;
    const float2* icf2 = (const float2*)icf;
    const float2* rk2  = (const float2*)g_relkg;
    const float* usrc   = hop ? g_u    : ext_user;
    const float* ucfsrc = hop ? g_ucf0 : ext_ucf;
    float2* udst2   = (float2*)g_u;
    float2* ucfdst2 = (float2*)(hop ? g_ucf1 : g_ucf0);
    float2* out2    = (float2*)out;

    int w = threadIdx.x >> 5, lane = threadIdx.x & 31;
    int u = blockIdx.x * 8 + w;
    if (u >= NU) return;

    float* sU  = sm + w * 320;
    float* sUC = sU + 64;
    float* sW  = sU + 128;
    float* sWC = sU + 192;
    int*   sCol = (int*)(sU + 256);

    int p0 = g_off[SEG_U + u];
    int n  = g_off[SEG_U + u + 1] - p0;
    if (n == 0) {
        float2 z = make_float2(0.f, 0.f);
        udst2[u * 32 + lane] = z;
        ucfdst2[u * 32 + lane] = z;
        return;
    }
    int pb = p0 - NEDGE;
    int nin = n < 64 ? n : 64;

    sU[lane]       = usrc[u * 64 + lane];
    sU[32 + lane]  = usrc[u * 64 + 32 + lane];
    sUC[lane]      = ucfsrc[u * 64 + lane];
    sUC[32 + lane] = ucfsrc[u * 64 + 32 + lane];
    if (lane < nin)      sCol[lane]      = g_perm[p0 + lane];
    if (lane + 32 < nin) sCol[lane + 32] = g_perm[p0 + lane + 32];
    __syncwarp();

    float2 ud, cd;
    int li = lane & 7, g = lane >> 3;

    for (int it = 0; it < 3; it++) {
        // ---- pass 1: dots, 4 pairs per warp concurrently (8 lanes each) ----
        for (int jb = 0; jb < nin; jb += 4) {
            int j = jb + g;
            bool act = j < nin;
            int col = act ? sCol[j] : 0;
            float4 a0 = rk4[col * 16 + li],     a1 = rk4[col * 16 + 8 + li];
            float4 b0 = icf4[col * 16 + li],    b1 = icf4[col * 16 + 8 + li];
            float4 u0 = *(const float4*)(sU + 4 * li);
            float4 u1 = *(const float4*)(sU + 32 + 4 * li);
            float4 c0 = *(const float4*)(sUC + 4 * li);
            float4 c1 = *(const float4*)(sUC + 32 + 4 * li);
            float s  = a0.x*u0.x + a0.y*u0.y + a0.z*u0.z + a0.w*u0.w
                     + a1.x*u1.x + a1.y*u1.y + a1.z*u1.z + a1.w*u1.w;
            float sc = b0.x*c0.x + b0.y*c0.y + b0.z*c0.z + b0.w*c0.w
                     + b1.x*c1.x + b1.y*c1.y + b1.z*c1.z + b1.w*c1.w;
            s  += __shfl_xor_sync(0xffffffffu, s, 1);
            sc += __shfl_xor_sync(0xffffffffu, sc, 1);
            s  += __shfl_xor_sync(0xffffffffu, s, 2);
            sc += __shfl_xor_sync(0xffffffffu, sc, 2);
            s  += __shfl_xor_sync(0xffffffffu, s, 4);
            sc += __shfl_xor_sync(0xffffffffu, sc, 4);
            if (li == 0 && act) { sW[j] = s; sWC[j] = sc; }
        }
        for (int j = 64; j < n; j++) {   // fallback (not taken for this data)
            int col = g_perm[p0 + j];
            float2 rk = rk2[col * 32 + lane];
            float2 iv = icf2[col * 32 + lane];
            float s  = warpsum(rk.x * sU[2 * lane] + rk.y * sU[2 * lane + 1]);
            float sc = warpsum(iv.x * sUC[2 * lane] + iv.y * sUC[2 * lane + 1]);
            if (lane == 0) { g_p[pb + j] = s; g_pcf[pb + j] = sc; }
        }
        __syncwarp();
        // ---- pass 2: weights = exp(sigmoid(dot)) (max-free, exact) ----
        float se = 0.f, sec = 0.f;
        if (lane < nin) {
            float e  = __expf(sigmoidf(sW[lane]));
            float ec = __expf(sigmoidf(sWC[lane]));
            sW[lane] = e; sWC[lane] = ec; se += e; sec += ec;
        }
        if (lane + 32 < nin) {
            float e  = __expf(sigmoidf(sW[lane + 32]));
            float ec = __expf(sigmoidf(sWC[lane + 32]));
            sW[lane + 32] = e; sWC[lane + 32] = ec; se += e; sec += ec;
        }
        for (int j = 64 + lane; j < n; j += 32) {
            float e  = __expf(sigmoidf(g_p[pb + j]));
            float ec = __expf(sigmoidf(g_pcf[pb + j]));
            g_p[pb + j] = e; g_pcf[pb + j] = ec;
            se += e; sec += ec;
        }
        se = warpsum(se); sec = warpsum(sec);
        float inv = 1.f / se, invc = 1.f / sec;
        __syncwarp();
        // ---- pass 3: weighted accumulation ----
        float2 A = make_float2(0.f, 0.f), B = make_float2(0.f, 0.f);
        for (int j = 0; j < nin; j++) {
            int col = sCol[j];
            float wp = sW[j] * inv, wc = sWC[j] * invc;
            float2 gv = kg2[col * 32 + lane];
            float2 iv = icf2[col * 32 + lane];
            A.x += wp * gv.x; A.y += wp * gv.y;
            B.x += wc * iv.x; B.y += wc * iv.y;
        }
        for (int j = 64; j < n; j++) {
            float wp = g_p[pb + j] * inv, wc = g_pcf[pb + j] * invc;
            int col = g_perm[p0 + j];
            float2 gv = kg2[col * 32 + lane];
            float2 iv = icf2[col * 32 + lane];
            A.x += wp * gv.x; A.y += wp * gv.y;
            B.x += wc * iv.x; B.y += wc * iv.y;
        }
        float ss = warpsum(A.x * A.x + A.y * A.y);
        float i1 = 1.f / fmaxf(sqrtf(ss), 1e-12f);
        ss = warpsum(B.x * B.x + B.y * B.y);
        float i2 = 1.f / fmaxf(sqrtf(ss), 1e-12f);
        ud.x = A.x * i1; ud.y = A.y * i1;
        cd.x = B.x * i2; cd.y = B.y * i2;
        if (it < 2) {
            __syncwarp();
            sU[2 * lane] = ud.x;  sU[2 * lane + 1] = ud.y;
            sUC[2 * lane] = cd.x; sUC[2 * lane + 1] = cd.y;
            __syncwarp();
        }
    }

    udst2[u * 32 + lane] = ud;
    ucfdst2[u * 32 + lane] = cd;
    int o1 = NE * 32 + u * 32 + lane;
    float2 o = out2[o1]; o.x += ud.x; o.y += ud.y; out2[o1] = o;
    int o2 = (NE + NU) * 32 + u * 32 + lane;
    o = out2[o2]; o.x += cd.x; o.y += cd.y; out2[o2] = o;
}

extern "C" void kernel_launch(void* const* d_in, const int* in_sizes, int n_in,
                              void* d_out, int out_size) {
    const float* user_emb = (const float*)d_in[0];
    const float* entity_emb = (const float*)d_in[1];
    const float* emb_cf = (const float*)d_in[2];
    const float* relw = (const float*)d_in[3];
    const float* W1 = (const float*)d_in[4];
    const float* B1 = (const float*)d_in[5];
    const float* W2 = (const float*)d_in[6];
    const float* B2 = (const float*)d_in[7];
    const int* eidx = (const int*)d_in[8];
    const int* etype = (const int*)d_in[9];
    const int* imat = (const int*)d_in[10];
    float* out = (float*)d_out;

    const int* heads = eidx;
    const int* tails = eidx + NEDGE;
    const float* ucf_ext = emb_cf;
    const float* icf_ext = emb_cf + NU * DM;

    k_init<<<2048, 256>>>(user_emb, entity_emb, emb_cf, out);
    k_count<<<3907, 256>>>(heads, imat);
    k_scan1<<<SCAN_NBLK, SCAN_BLK>>>();
    k_scan2<<<1, SCAN_BLK>>>();
    k_scan3<<<SCAN_NBLK, SCAN_BLK>>>();
    k_scatter<<<3907, 256>>>(heads, tails, etype, imat);

    for (int h = 0; h < 2; h++) {
        k_entity<<<NE / 8, 256>>>(entity_emb, h, relw,
                                  W1 + h * DM * DM, B1 + h * DM,
                                  W2 + h * DM * DM, B2 + h * DM, out);
        k_item<<<NI / 8, 256>>>(ucf_ext, h, out);
        k_userhop<<<(NU + 7) / 8, 256>>>(user_emb, ucf_ext, entity_emb, icf_ext,
                                         h, out);
    }
    (void)in_sizes; (void)n_in; (void)out_size;
}

// round 9
// speedup vs baseline: 1.4897x; 1.0136x over previous
#include <cuda_runtime.h>
#include <cuda_fp16.h>
#include <math.h>

#define NU 100000
#define NI 50000
#define NE 120000
#define NR 32
#define DM 64
#define NEDGE 1000000
#define NCF 1000000

#define SEG_U 120000
#define SEG_I 220000
#define NSEG 270000
#define SCAN_N 270001
#define SCAN_BLK 1024
#define SCAN_NBLK 264

__device__ int   g_cnt[SCAN_NBLK * SCAN_BLK];
__device__ int   g_off[SCAN_NBLK * SCAN_BLK + 1];
__device__ int   g_cur[NSEG];
__device__ int   g_perm[NEDGE + 2 * NCF];   // PAYLOADS: entity=(tail<<5)|type, user=col, item=row
__device__ int   g_bsum[SCAN_BLK];
__device__ int   g_boff[SCAN_BLK];

__device__ float g_entA[NE * DM];
__device__ float g_entB[NE * DM];
__device__ float g_u[NU * DM];
__device__ float g_ucf0[NU * DM];
__device__ float g_ucf1[NU * DM];
__device__ float g_icf0[NI * DM];
__device__ float g_icf1[NI * DM];
__device__ float g_p[NCF];
__device__ float g_pcf[NCF];

// half item tables gathered by k_userhop (col < NI only)
__device__ __half g_relkg_h[NI * DM];
__device__ __half g_kg_h[NI * DM];
__device__ __half g_icf_h[NI * DM];

__device__ __forceinline__ float warpsum(float v) {
    #pragma unroll
    for (int o = 16; o; o >>= 1) v += __shfl_xor_sync(0xffffffffu, v, o);
    return v;
}
__device__ __forceinline__ float lrelu(float x) { return x > 0.f ? x : 0.01f * x; }
__device__ __forceinline__ float sigmoidf(float x) { return 1.f / (1.f + __expf(-x)); }

// init: out = concat(entity, user, ucf, icf) + zero counters + seed hop-0 icf_h
__global__ void k_init(const float* __restrict__ ue, const float* __restrict__ ee,
                       const float* __restrict__ cf, float* __restrict__ out) {
    const int total = (NE + NU + NU + NI) * DM;
    for (int i = blockIdx.x * blockDim.x + threadIdx.x; i < total; i += gridDim.x * blockDim.x) {
        if (i < SCAN_NBLK * SCAN_BLK) {
            g_cnt[i] = 0;
            if (i < NSEG) g_cur[i] = 0;
        }
        float v;
        if (i < NE * DM)                   v = ee[i];
        else if (i < (NE + NU) * DM)       v = ue[i - NE * DM];
        else if (i < (NE + 2 * NU) * DM)   v = cf[i - (NE + NU) * DM];
        else {
            int d = i - (NE + 2 * NU) * DM;
            v = cf[NU * DM + d];
            g_icf_h[d] = __float2half(v);   // hop-0 icf table
        }
        out[i] = v;
    }
}

__global__ void k_count(const int* __restrict__ heads, const int* __restrict__ imat) {
    for (int i = blockIdx.x * blockDim.x + threadIdx.x; i < NEDGE; i += gridDim.x * blockDim.x) {
        atomicAdd(&g_cnt[heads[i]], 1);
        atomicAdd(&g_cnt[SEG_U + imat[2 * i]], 1);
        atomicAdd(&g_cnt[SEG_I + imat[2 * i + 1]], 1);
    }
}

__global__ void k_scan1() {
    __shared__ int sh[SCAN_BLK];
    int t = threadIdx.x;
    int i = blockIdx.x * SCAN_BLK + t;
    sh[t] = (i < SCAN_N) ? g_cnt[i] : 0;
    __syncthreads();
    for (int s = SCAN_BLK / 2; s > 0; s >>= 1) {
        if (t < s) sh[t] += sh[t + s];
        __syncthreads();
    }
    if (t == 0) g_bsum[blockIdx.x] = sh[0];
}
__global__ void k_scan2() {
    __shared__ int sh[SCAN_BLK];
    int t = threadIdx.x;
    int v = (t < SCAN_NBLK) ? g_bsum[t] : 0;
    sh[t] = v;
    __syncthreads();
    for (int d = 1; d < SCAN_BLK; d <<= 1) {
        int x = (t >= d) ? sh[t - d] : 0;
        __syncthreads();
        sh[t] += x;
        __syncthreads();
    }
    if (t < SCAN_NBLK) g_boff[t] = sh[t] - v;
}
__global__ void k_scan3() {
    __shared__ int sh[SCAN_BLK];
    int t = threadIdx.x;
    int i = blockIdx.x * SCAN_BLK + t;
    int v = (i < SCAN_N) ? g_cnt[i] : 0;
    sh[t] = v;
    __syncthreads();
    for (int d = 1; d < SCAN_BLK; d <<= 1) {
        int x = (t >= d) ? sh[t - d] : 0;
        __syncthreads();
        sh[t] += x;
        __syncthreads();
    }
    if (i < SCAN_N) g_off[i] = g_boff[blockIdx.x] + sh[t] - v;
}

__global__ void k_scatter(const int* __restrict__ heads, const int* __restrict__ tails,
                          const int* __restrict__ etype, const int* __restrict__ imat) {
    for (int i = blockIdx.x * blockDim.x + threadIdx.x; i < NEDGE; i += gridDim.x * blockDim.x) {
        int h = heads[i];
        int p = g_off[h] + atomicAdd(&g_cur[h], 1);
        g_perm[p] = (tails[i] << 5) | etype[i];
        int row = imat[2 * i], col = imat[2 * i + 1];
        int r = SEG_U + row;
        p = g_off[r] + atomicAdd(&g_cur[r], 1);
        g_perm[p] = col;
        int c = SEG_I + col;
        p = g_off[c] + atomicAdd(&g_cur[c], 1);
        g_perm[p] = row;
    }
}

// entity aggregation (warp-per-entity) + fused half-table production:
// relkg_h[e] = half(mean-rel * entin[e]); kg_h[e] = half(entin[e])  (items only)
__global__ void k_entity(const float* __restrict__ ext_ent, int hop,
                         const float* __restrict__ relw,
                         const float* __restrict__ W1, const float* __restrict__ b1,
                         const float* __restrict__ W2, const float* __restrict__ b2,
                         float* __restrict__ out) {
    __shared__ float s_rel[NR * DM];
    __shared__ float sW1[DM * 65];
    __shared__ float sW2[DM * 65];
    __shared__ float sb1[DM], sb2[DM];
    int t = threadIdx.x;
    for (int i = t; i < NR * DM; i += blockDim.x) s_rel[i] = relw[i];
    for (int i = t; i < DM * DM; i += blockDim.x) {
        int d = i >> 6, k = i & 63;
        sW1[d * 65 + k] = W1[i];
        sW2[d * 65 + k] = W2[i];
    }
    if (t < DM) { sb1[t] = b1[t]; sb2[t] = b2[t]; }
    __syncthreads();

    const float* entin = hop ? g_entB : ext_ent;
    float* entout      = hop ? g_entA : g_entB;

    int lane = t & 31;
    int e = blockIdx.x * (blockDim.x >> 5) + (t >> 5);
    if (e >= NE) return;
    int p0 = g_off[e], p1 = g_off[e + 1];
    bool eItem = e < NI;

    float a10 = 0, a11 = 0, a20 = 0, a21 = 0, ar0 = 0, ar1 = 0;
    int nc = 0;
    for (int p = p0; p < p1; p++) {
        int packed = g_perm[p];
        int tl = packed >> 5, ty = packed & 31;
        float r0 = s_rel[ty * 64 + lane], r1 = s_rel[ty * 64 + 32 + lane];
        float t0 = entin[tl * 64 + lane], t1 = entin[tl * 64 + 32 + lane];
        bool cross = eItem != (tl < NI);
        if (cross) { a10 += t0 * r0; a11 += t1 * r1; nc++; }
        else       { a20 += t0 + r0; a21 += t1 + r1; }
        ar0 += r0; ar1 += r1;
    }
    int n = p1 - p0;

    if (eItem) {
        float dn = 1.f / fmaxf((float)n, 1.f);
        float e0 = entin[e * 64 + lane], e1 = entin[e * 64 + 32 + lane];
        g_relkg_h[e * 64 + lane]      = __float2half((ar0 * dn) * e0);
        g_relkg_h[e * 64 + 32 + lane] = __float2half((ar1 * dn) * e1);
        g_kg_h[e * 64 + lane]         = __float2half(e0);
        g_kg_h[e * 64 + 32 + lane]    = __float2half(e1);
    }

    float i1 = 1.f / fmaxf((float)nc, 1.f);
    float i2 = 1.f / fmaxf((float)(n - nc), 1.f);
    a10 *= i1; a11 *= i1; a20 *= i2; a21 *= i2;

    float o10 = sb1[lane], o11 = sb1[lane + 32];
    float o20 = sb2[lane], o21 = sb2[lane + 32];
    #pragma unroll
    for (int k = 0; k < 64; k++) {
        float a = __shfl_sync(0xffffffffu, (k < 32) ? a10 : a11, k & 31);
        o10 += a * sW1[lane * 65 + k];
        o11 += a * sW1[(lane + 32) * 65 + k];
    }
    #pragma unroll
    for (int k = 0; k < 64; k++) {
        float a = __shfl_sync(0xffffffffu, (k < 32) ? a20 : a21, k & 31);
        o20 += a * sW2[lane * 65 + k];
        o21 += a * sW2[(lane + 32) * 65 + k];
    }
    float v0 = 0.5f * (lrelu(o10) + lrelu(o20));
    float v1 = 0.5f * (lrelu(o11) + lrelu(o21));
    float ss = warpsum(v0 * v0 + v1 * v1);
    float inv = 1.f / fmaxf(sqrtf(ss), 1e-12f);
    v0 *= inv; v1 *= inv;
    entout[e * 64 + lane] = v0;
    entout[e * 64 + 32 + lane] = v1;
    out[e * 64 + lane] += v0;
    out[e * 64 + 32 + lane] += v1;
}

// item aggregation (float2 loads); also writes next hop's icf half table
__global__ void k_item(const float* __restrict__ ext_ucf, int hop,
                       float* __restrict__ out) {
    const float2* ucfin2 = (const float2*)(hop ? g_ucf0 : ext_ucf);
    float2* icfout2      = (float2*)(hop ? g_icf1 : g_icf0);
    float2* out2         = (float2*)out;
    int t = threadIdx.x, lane = t & 31;
    int c = blockIdx.x * (blockDim.x >> 5) + (t >> 5);
    if (c >= NI) return;
    int p0 = g_off[SEG_I + c], p1 = g_off[SEG_I + c + 1];
    float2 acc = make_float2(0.f, 0.f);
    for (int p = p0; p < p1; p++) {
        int row = g_perm[p];
        float2 v = ucfin2[row * 32 + lane];
        acc.x += v.x; acc.y += v.y;
    }
    float dn = 1.f / fmaxf((float)(p1 - p0), 1.f);
    acc.x *= dn; acc.y *= dn;
    float ss = warpsum(acc.x * acc.x + acc.y * acc.y);
    float inv = 1.f / fmaxf(sqrtf(ss), 1e-12f);
    acc.x *= inv; acc.y *= inv;
    icfout2[c * 32 + lane] = acc;
    ((__half2*)g_icf_h)[c * 32 + lane] = __floats2half2_rn(acc.x, acc.y);
    int ob = (NE + 2 * NU) * 32 + c * 32 + lane;
    float2 o = out2[ob];
    o.x += acc.x; o.y += acc.y;
    out2[ob] = o;
}

// fused user kernel: proven structure, half item tables (gathered bytes halved)
__global__ void __launch_bounds__(256) k_userhop(
        const float* __restrict__ ext_user, const float* __restrict__ ext_ucf,
        int hop, float* __restrict__ out)
{
    __shared__ __align__(16) float sm[8 * 320];   // per warp: U64|UC64|W64|WC64|COL64

    const uint4* rkh4    = (const uint4*)g_relkg_h;   // 8 uint4 (= 64 halves) per row
    const uint4* icfh4   = (const uint4*)g_icf_h;
    const __half2* rkh2  = (const __half2*)g_relkg_h;
    const __half2* kgh2  = (const __half2*)g_kg_h;
    const __half2* icfh2 = (const __half2*)g_icf_h;
    const float* usrc    = hop ? g_u    : ext_user;
    const float* ucfsrc  = hop ? g_ucf0 : ext_ucf;
    float2* udst2   = (float2*)g_u;
    float2* ucfdst2 = (float2*)(hop ? g_ucf1 : g_ucf0);
    float2* out2    = (float2*)out;

    int w = threadIdx.x >> 5, lane = threadIdx.x & 31;
    int u = blockIdx.x * 8 + w;
    if (u >= NU) return;

    float* sU  = sm + w * 320;
    float* sUC = sU + 64;
    float* sW  = sU + 128;
    float* sWC = sU + 192;
    int*   sCol = (int*)(sU + 256);

    int p0 = g_off[SEG_U + u];
    int n  = g_off[SEG_U + u + 1] - p0;
    if (n == 0) {
        float2 z = make_float2(0.f, 0.f);
        udst2[u * 32 + lane] = z;
        ucfdst2[u * 32 + lane] = z;
        return;
    }
    int pb = p0 - NEDGE;
    int nin = n < 64 ? n : 64;

    sU[lane]       = usrc[u * 64 + lane];
    sU[32 + lane]  = usrc[u * 64 + 32 + lane];
    sUC[lane]      = ucfsrc[u * 64 + lane];
    sUC[32 + lane] = ucfsrc[u * 64 + 32 + lane];
    if (lane < nin)      sCol[lane]      = g_perm[p0 + lane];
    if (lane + 32 < nin) sCol[lane + 32] = g_perm[p0 + lane + 32];
    __syncwarp();

    float2 ud, cd;
    int li = lane & 7, g = lane >> 3;

    for (int it = 0; it < 3; it++) {
        // ---- pass 1: dots, 4 pairs per warp (8 lanes each), half rows ----
        for (int jb = 0; jb < nin; jb += 4) {
            int j = jb + g;
            bool act = j < nin;
            int col = act ? sCol[j] : 0;
            uint4 ra = rkh4[col * 8 + li];     // halves for dims 8li..8li+7
            uint4 ba = icfh4[col * 8 + li];
            float2 r0 = __half22float2(*(const __half2*)&ra.x);
            float2 r1 = __half22float2(*(const __half2*)&ra.y);
            float2 r2 = __half22float2(*(const __half2*)&ra.z);
            float2 r3 = __half22float2(*(const __half2*)&ra.w);
            float2 b0 = __half22float2(*(const __half2*)&ba.x);
            float2 b1 = __half22float2(*(const __half2*)&ba.y);
            float2 b2 = __half22float2(*(const __half2*)&ba.z);
            float2 b3 = __half22float2(*(const __half2*)&ba.w);
            float4 u0 = *(const float4*)(sU + 8 * li);
            float4 u1 = *(const float4*)(sU + 8 * li + 4);
            float4 c0 = *(const float4*)(sUC + 8 * li);
            float4 c1 = *(const float4*)(sUC + 8 * li + 4);
            float s  = r0.x*u0.x + r0.y*u0.y + r1.x*u0.z + r1.y*u0.w
                     + r2.x*u1.x + r2.y*u1.y + r3.x*u1.z + r3.y*u1.w;
            float sc = b0.x*c0.x + b0.y*c0.y + b1.x*c0.z + b1.y*c0.w
                     + b2.x*c1.x + b2.y*c1.y + b3.x*c1.z + b3.y*c1.w;
            s  += __shfl_xor_sync(0xffffffffu, s, 1);
            sc += __shfl_xor_sync(0xffffffffu, sc, 1);
            s  += __shfl_xor_sync(0xffffffffu, s, 2);
            sc += __shfl_xor_sync(0xffffffffu, sc, 2);
            s  += __shfl_xor_sync(0xffffffffu, s, 4);
            sc += __shfl_xor_sync(0xffffffffu, sc, 4);
            if (li == 0 && act) { sW[j] = s; sWC[j] = sc; }
        }
        for (int j = 64; j < n; j++) {   // fallback (not taken for this data)
            int col = g_perm[p0 + j];
            float2 rk = __half22float2(rkh2[col * 32 + lane]);
            float2 iv = __half22float2(icfh2[col * 32 + lane]);
            float s  = warpsum(rk.x * sU[2 * lane] + rk.y * sU[2 * lane + 1]);
            float sc = warpsum(iv.x * sUC[2 * lane] + iv.y * sUC[2 * lane + 1]);
            if (lane == 0) { g_p[pb + j] = s; g_pcf[pb + j] = sc; }
        }
        __syncwarp();
        // ---- pass 2: weights = exp(sigmoid(dot)) (max-free, exact) ----
        float se = 0.f, sec = 0.f;
        if (lane < nin) {
            float e  = __expf(sigmoidf(sW[lane]));
            float ec = __expf(sigmoidf(sWC[lane]));
            sW[lane] = e; sWC[lane] = ec; se += e; sec += ec;
        }
        if (lane + 32 < nin) {
            float e  = __expf(sigmoidf(sW[lane + 32]));
            float ec = __expf(sigmoidf(sWC[lane + 32]));
            sW[lane + 32] = e; sWC[lane + 32] = ec; se += e; sec += ec;
        }
        for (int j = 64 + lane; j < n; j += 32) {
            float e  = __expf(sigmoidf(g_p[pb + j]));
            float ec = __expf(sigmoidf(g_pcf[pb + j]));
            g_p[pb + j] = e; g_pcf[pb + j] = ec;
            se += e; sec += ec;
        }
        se = warpsum(se); sec = warpsum(sec);
        float inv = 1.f / se, invc = 1.f / sec;
        __syncwarp();
        // ---- pass 3: weighted accumulation (half rows) ----
        float2 A = make_float2(0.f, 0.f), B = make_float2(0.f, 0.f);
        for (int j = 0; j < nin; j++) {
            int col = sCol[j];
            float wp = sW[j] * inv, wc = sWC[j] * invc;
            float2 gv = __half22float2(kgh2[col * 32 + lane]);
            float2 iv = __half22float2(icfh2[col * 32 + lane]);
            A.x += wp * gv.x; A.y += wp * gv.y;
            B.x += wc * iv.x; B.y += wc * iv.y;
        }
        for (int j = 64; j < n; j++) {
            float wp = g_p[pb + j] * inv, wc = g_pcf[pb + j] * invc;
            int col = g_perm[p0 + j];
            float2 gv = __half22float2(kgh2[col * 32 + lane]);
            float2 iv = __half22float2(icfh2[col * 32 + lane]);
            A.x += wp * gv.x; A.y += wp * gv.y;
            B.x += wc * iv.x; B.y += wc * iv.y;
        }
        float ss = warpsum(A.x * A.x + A.y * A.y);
        float i1 = 1.f / fmaxf(sqrtf(ss), 1e-12f);
        ss = warpsum(B.x * B.x + B.y * B.y);
        float i2 = 1.f / fmaxf(sqrtf(ss), 1e-12f);
        ud.x = A.x * i1; ud.y = A.y * i1;
        cd.x = B.x * i2; cd.y = B.y * i2;
        if (it < 2) {
            __syncwarp();
            sU[2 * lane] = ud.x;  sU[2 * lane + 1] = ud.y;
            sUC[2 * lane] = cd.x; sUC[2 * lane + 1] = cd.y;
            __syncwarp();
        }
    }

    udst2[u * 32 + lane] = ud;
    ucfdst2[u * 32 + lane] = cd;
    int o1 = NE * 32 + u * 32 + lane;
    float2 o = out2[o1]; o.x += ud.x; o.y += ud.y; out2[o1] = o;
    int o2 = (NE + NU) * 32 + u * 32 + lane;
    o = out2[o2]; o.x += cd.x; o.y += cd.y; out2[o2] = o;
}

extern "C" void kernel_launch(void* const* d_in, const int* in_sizes, int n_in,
                              void* d_out, int out_size) {
    const float* user_emb = (const float*)d_in[0];
    const float* entity_emb = (const float*)d_in[1];
    const float* emb_cf = (const float*)d_in[2];
    const float* relw = (const float*)d_in[3];
    const float* W1 = (const float*)d_in[4];
    const float* B1 = (const float*)d_in[5];
    const float* W2 = (const float*)d_in[6];
    const float* B2 = (const float*)d_in[7];
    const int* eidx = (const int*)d_in[8];
    const int* etype = (const int*)d_in[9];
    const int* imat = (const int*)d_in[10];
    float* out = (float*)d_out;

    const int* heads = eidx;
    const int* tails = eidx + NEDGE;
    const float* ucf_ext = emb_cf;

    k_init<<<2048, 256>>>(user_emb, entity_emb, emb_cf, out);
    k_count<<<3907, 256>>>(heads, imat);
    k_scan1<<<SCAN_NBLK, SCAN_BLK>>>();
    k_scan2<<<1, SCAN_BLK>>>();
    k_scan3<<<SCAN_NBLK, SCAN_BLK>>>();
    k_scatter<<<3907, 256>>>(heads, tails, etype, imat);

    for (int h = 0; h < 2; h++) {
        k_entity<<<NE / 8, 256>>>(entity_emb, h, relw,
                                  W1 + h * DM * DM, B1 + h * DM,
                                  W2 + h * DM * DM, B2 + h * DM, out);
        // userhop BEFORE item: item(h) writes icf_h for hop h+1; userhop(h)
        // must read the hop-h version (k_init's for h=0, item(0)'s for h=1).
        k_userhop<<<(NU + 7) / 8, 256>>>(user_emb, ucf_ext, h, out);
        k_item<<<NI / 8, 256>>>(ucf_ext, h, out);
    }
    (void)in_sizes; (void)n_in; (void)out_size;
}